// round 7
// baseline (speedup 1.0000x reference)
#include <cuda_runtime.h>
#include <cuda_bf16.h>
#include <cstdint>

#define NB 1024
#define NT 256
#define NC 512
#define NH 64

// ---------------- scratch (static device globals; no allocation) ----------------
__device__ __nv_bfloat16 g_qh[NB*NT*NH];
__device__ __nv_bfloat16 g_ql[NB*NT*NH];
__device__ __nv_bfloat16 g_kh[NB*NT*NH];
__device__ __nv_bfloat16 g_kl[NB*NT*NH];
__device__ __nv_bfloat16 g_vh[NB*NT*NH];
__device__ __nv_bfloat16 g_vl[NB*NT*NH];
__device__ __nv_bfloat16 g_wth[192*512];   // [n192][k] transposed hi
__device__ __nv_bfloat16 g_wtl[192*512];   // [n192][k] transposed lo

// ---------------- helpers ----------------
__device__ __forceinline__ uint32_t smem_u32(const void* p){
  uint32_t a;
  asm("{ .reg .u64 t; cvta.to.shared.u64 t, %1; cvt.u32.u64 %0, t; }" : "=r"(a) : "l"(p));
  return a;
}
__device__ __forceinline__ void mma16816(float* d, const uint32_t* a, const uint32_t* b){
  asm volatile(
    "mma.sync.aligned.m16n8k16.row.col.f32.bf16.bf16.f32 "
    "{%0,%1,%2,%3},{%4,%5,%6,%7},{%8,%9},{%0,%1,%2,%3};\n"
    : "+f"(d[0]), "+f"(d[1]), "+f"(d[2]), "+f"(d[3])
    : "r"(a[0]), "r"(a[1]), "r"(a[2]), "r"(a[3]), "r"(b[0]), "r"(b[1]));
}
__device__ __forceinline__ void cp_async16(uint32_t saddr, const void* g){
  asm volatile("cp.async.cg.shared.global [%0], [%1], 16;" :: "r"(saddr), "l"(g));
}
#define CP_COMMIT() asm volatile("cp.async.commit_group;" ::: "memory")
#define CP_WAIT0()  asm volatile("cp.async.wait_group 0;" ::: "memory")

__device__ __forceinline__ uint32_t pack_hi2(float a, float b){
  __nv_bfloat162 t = __floats2bfloat162_rn(a, b);
  return *reinterpret_cast<uint32_t*>(&t);
}
__device__ __forceinline__ uint32_t pack_lo2(float a, float b){
  float ah = __bfloat162float(__float2bfloat16(a));
  float bh = __bfloat162float(__float2bfloat16(b));
  __nv_bfloat162 t = __floats2bfloat162_rn(a - ah, b - bh);
  return *reinterpret_cast<uint32_t*>(&t);
}

// ---------------- kernel 0: split + transpose weights ----------------
__global__ void prep_w_kernel(const float* __restrict__ Wq,
                              const float* __restrict__ Wk,
                              const float* __restrict__ Wv){
  int idx = blockIdx.x*blockDim.x + threadIdx.x;
  if (idx >= 192*512) return;
  int n192 = idx >> 9, k = idx & 511;
  int mat = n192 >> 6, n = n192 & 63;
  const float* W = (mat == 0) ? Wq : (mat == 1 ? Wk : Wv);
  float v = W[k*NH + n];
  __nv_bfloat16 h = __float2bfloat16(v);
  g_wth[idx] = h;
  g_wtl[idx] = __float2bfloat16(v - __bfloat162float(h));
}

// ---------------- kernel 1: fused QKV projection (split-bf16 MMA) ----------------
// CTA: 128 rows x 192 cols (Q|K|V), K-chunks of 64. 8 warps = 2(m) x 4(n), warp tile 64x48.
// smem (halves): xh[9216] xl[9216] | Wbuf0: wh[13824] wl[13824] | Wbuf1: wh wl
// W double-buffered via cp.async; x register-prefetched + converted to hi/lo bf16.
#define K1_XOFF  0
#define K1_WOFF  18432
#define K1_WBUF  27648
#define K1_SMEM  ((18432 + 2*27648)*2)

__global__ __launch_bounds__(256, 1) void qkv_kernel(const float* __restrict__ x){
  extern __shared__ __nv_bfloat16 sm1[];
  __nv_bfloat16* xh = sm1;
  __nv_bfloat16* xl = sm1 + 9216;
  const uint32_t sb = smem_u32(sm1);

  const int t = threadIdx.x;
  const int w = t >> 5, lane = t & 31, g = lane >> 2, t4 = lane & 3;
  const int mw = w >> 2, nw = w & 3;          // 2(m) x 4(n)
  const int row0 = blockIdx.x * 128;

  float acc[4][6][4];
  #pragma unroll
  for (int mt = 0; mt < 4; mt++)
    #pragma unroll
    for (int nt = 0; nt < 6; nt++)
      #pragma unroll
      for (int e = 0; e < 4; e++) acc[mt][nt][e] = 0.f;

  float4 xr[8];

  #define LDG_X(kc) { \
    _Pragma("unroll") \
    for (int i = 0; i < 8; i++){ \
      int idx4 = i*256 + t; \
      int r = idx4 >> 4, c4 = (idx4 & 15) << 2; \
      xr[i] = *reinterpret_cast<const float4*>(x + (size_t)(row0 + r)*NC + (kc)*64 + c4); \
    } }

  #define STS_X() { \
    _Pragma("unroll") \
    for (int i = 0; i < 8; i++){ \
      int idx4 = i*256 + t; \
      int r = idx4 >> 4, c4 = (idx4 & 15) << 2; \
      float4 v = xr[i]; \
      __nv_bfloat162 h01, h23, l01, l23; \
      h01.x = __float2bfloat16(v.x); l01.x = __float2bfloat16(v.x - __bfloat162float(h01.x)); \
      h01.y = __float2bfloat16(v.y); l01.y = __float2bfloat16(v.y - __bfloat162float(h01.y)); \
      h23.x = __float2bfloat16(v.z); l23.x = __float2bfloat16(v.z - __bfloat162float(h23.x)); \
      h23.y = __float2bfloat16(v.w); l23.y = __float2bfloat16(v.w - __bfloat162float(h23.y)); \
      *reinterpret_cast<__nv_bfloat162*>(&xh[r*72 + c4    ]) = h01; \
      *reinterpret_cast<__nv_bfloat162*>(&xh[r*72 + c4 + 2]) = h23; \
      *reinterpret_cast<__nv_bfloat162*>(&xl[r*72 + c4    ]) = l01; \
      *reinterpret_cast<__nv_bfloat162*>(&xl[r*72 + c4 + 2]) = l23; \
    } }

  // W tile for chunk kc -> buffer b via cp.async (idx<1536: hi matrix, idx>=1536: lo; 16B each)
  // NOTE: 1536 is NOT a power of two — must use subtraction, not a mask (R4/R6 bug).
  #define CPA_W(kc, b) { \
    _Pragma("unroll") \
    for (int i = 0; i < 12; i++){ \
      int idx = i*256 + t; \
      int hl = (idx >= 1536) ? 1 : 0; \
      int j = hl ? (idx - 1536) : idx; \
      int n = j >> 3, c8 = j & 7; \
      const __nv_bfloat16* src = (hl ? g_wtl : g_wth) + n*512 + (kc)*64 + c8*8; \
      uint32_t dst = sb + (uint32_t)(K1_WOFF + (b)*K1_WBUF + hl*13824 + n*72 + c8*8) * 2u; \
      cp_async16(dst, src); \
    } \
    CP_COMMIT(); }

  // prologue: x chunk 0 staged, W chunk 0 in flight
  LDG_X(0); STS_X(); CPA_W(0, 0);

  for (int kc = 0; kc < 8; kc++){
    const int buf = kc & 1;
    CP_WAIT0();                 // W[kc] landed
    __syncthreads();            // + x[kc] STS visible to all

    if (kc < 7){
      CPA_W(kc+1, buf^1);       // overlaps the MMA block below
      LDG_X(kc+1);              // register prefetch, overlaps MMA
    }

    const __nv_bfloat16* whb = sm1 + K1_WOFF + buf*K1_WBUF;
    const __nv_bfloat16* wlb = whb + 13824;

    #pragma unroll
    for (int ks = 0; ks < 4; ks++){
      const int ko = ks*16;
      uint32_t ah[4][4], al[4][4];
      #pragma unroll
      for (int mt = 0; mt < 4; mt++){
        int rb = mw*64 + mt*16;
        ah[mt][0] = *reinterpret_cast<const uint32_t*>(&xh[(rb+g  )*72 + ko + 2*t4    ]);
        ah[mt][1] = *reinterpret_cast<const uint32_t*>(&xh[(rb+g+8)*72 + ko + 2*t4    ]);
        ah[mt][2] = *reinterpret_cast<const uint32_t*>(&xh[(rb+g  )*72 + ko + 2*t4 + 8]);
        ah[mt][3] = *reinterpret_cast<const uint32_t*>(&xh[(rb+g+8)*72 + ko + 2*t4 + 8]);
        al[mt][0] = *reinterpret_cast<const uint32_t*>(&xl[(rb+g  )*72 + ko + 2*t4    ]);
        al[mt][1] = *reinterpret_cast<const uint32_t*>(&xl[(rb+g+8)*72 + ko + 2*t4    ]);
        al[mt][2] = *reinterpret_cast<const uint32_t*>(&xl[(rb+g  )*72 + ko + 2*t4 + 8]);
        al[mt][3] = *reinterpret_cast<const uint32_t*>(&xl[(rb+g+8)*72 + ko + 2*t4 + 8]);
      }
      uint32_t bb[6][2];
      #pragma unroll
      for (int nt = 0; nt < 6; nt++){
        int nb = nw*48 + nt*8;
        bb[nt][0] = *reinterpret_cast<const uint32_t*>(&whb[(nb+g)*72 + ko + 2*t4    ]);
        bb[nt][1] = *reinterpret_cast<const uint32_t*>(&whb[(nb+g)*72 + ko + 2*t4 + 8]);
      }
      #pragma unroll
      for (int nt = 0; nt < 6; nt++)            // pass 1: xh * wh
        #pragma unroll
        for (int mt = 0; mt < 4; mt++) mma16816(acc[mt][nt], ah[mt], bb[nt]);
      #pragma unroll
      for (int nt = 0; nt < 6; nt++)            // pass 2: xl * wh
        #pragma unroll
        for (int mt = 0; mt < 4; mt++) mma16816(acc[mt][nt], al[mt], bb[nt]);
      #pragma unroll
      for (int nt = 0; nt < 6; nt++){
        int nb = nw*48 + nt*8;
        bb[nt][0] = *reinterpret_cast<const uint32_t*>(&wlb[(nb+g)*72 + ko + 2*t4    ]);
        bb[nt][1] = *reinterpret_cast<const uint32_t*>(&wlb[(nb+g)*72 + ko + 2*t4 + 8]);
      }
      #pragma unroll
      for (int nt = 0; nt < 6; nt++)            // pass 3: xh * wl
        #pragma unroll
        for (int mt = 0; mt < 4; mt++) mma16816(acc[mt][nt], ah[mt], bb[nt]);
    }

    __syncthreads();            // all warps done reading x[kc] smem
    if (kc < 7){ STS_X(); }     // stage x[kc+1]
  }

  // epilogue: split fp32 accum -> hi/lo bf16 scratch
  #pragma unroll
  for (int mt = 0; mt < 4; mt++){
    #pragma unroll
    for (int nt = 0; nt < 6; nt++){
      int col = nw*48 + nt*8 + 2*t4;
      int mat = col >> 6, h = col & 63;
      __nv_bfloat16* dh = (mat == 0) ? g_qh : (mat == 1 ? g_kh : g_vh);
      __nv_bfloat16* dl = (mat == 0) ? g_ql : (mat == 1 ? g_kl : g_vl);
      int r0g = row0 + mw*64 + mt*16 + g;
      float c0 = acc[mt][nt][0], c1 = acc[mt][nt][1];
      float c2 = acc[mt][nt][2], c3 = acc[mt][nt][3];
      __nv_bfloat162 hh, ll;
      hh.x = __float2bfloat16(c0); ll.x = __float2bfloat16(c0 - __bfloat162float(hh.x));
      hh.y = __float2bfloat16(c1); ll.y = __float2bfloat16(c1 - __bfloat162float(hh.y));
      *reinterpret_cast<__nv_bfloat162*>(&dh[(size_t)r0g*NH + h]) = hh;
      *reinterpret_cast<__nv_bfloat162*>(&dl[(size_t)r0g*NH + h]) = ll;
      hh.x = __float2bfloat16(c2); ll.x = __float2bfloat16(c2 - __bfloat162float(hh.x));
      hh.y = __float2bfloat16(c3); ll.y = __float2bfloat16(c3 - __bfloat162float(hh.y));
      *reinterpret_cast<__nv_bfloat162*>(&dh[(size_t)(r0g+8)*NH + h]) = hh;
      *reinterpret_cast<__nv_bfloat162*>(&dl[(size_t)(r0g+8)*NH + h]) = ll;
    }
  }
  #undef LDG_X
  #undef STS_X
  #undef CPA_W
}

// ---------------- kernel 2: causal attention (flash-style, split-bf16 MMA) ----------------
#define A_QH 0
#define A_QL 9216
#define A_KH 18432
#define A_KL 36864
#define A_VH 55296
#define A_VL 72320
#define A_TOT 89344
#define K2_SMEM (A_TOT*2)
#define VSTR 266

__global__ __launch_bounds__(256, 1) void attn_kernel(float* __restrict__ out){
  extern __shared__ __nv_bfloat16 sm2[];
  __nv_bfloat16* qh  = sm2 + A_QH;
  __nv_bfloat16* ql  = sm2 + A_QL;
  __nv_bfloat16* kh  = sm2 + A_KH;
  __nv_bfloat16* kl  = sm2 + A_KL;
  __nv_bfloat16* vth = sm2 + A_VH;
  __nv_bfloat16* vtl = sm2 + A_VL;

  const int b   = blockIdx.x >> 1;
  const int blk = blockIdx.x & 1;
  const int t = threadIdx.x, w = t >> 5, lane = t & 31, g = lane >> 2, t4 = lane & 3;
  const int nk = (blk + 1) * 128;
  const size_t base = (size_t)b * (NT*NH);

  #pragma unroll
  for (int i = 0; i < 8; i++){
    int idx4 = i*256 + t;
    int r = idx4 >> 4, c4 = (idx4 & 15) << 2;
    *reinterpret_cast<uint2*>(&qh[r*72 + c4]) =
        *reinterpret_cast<const uint2*>(&g_qh[base + (size_t)(blk*128 + r)*NH + c4]);
    *reinterpret_cast<uint2*>(&ql[r*72 + c4]) =
        *reinterpret_cast<const uint2*>(&g_ql[base + (size_t)(blk*128 + r)*NH + c4]);
  }
  for (int idx4 = t; idx4 < nk*16; idx4 += 256){
    int r = idx4 >> 4, c4 = (idx4 & 15) << 2;
    *reinterpret_cast<uint2*>(&kh[r*72 + c4]) =
        *reinterpret_cast<const uint2*>(&g_kh[base + (size_t)r*NH + c4]);
    *reinterpret_cast<uint2*>(&kl[r*72 + c4]) =
        *reinterpret_cast<const uint2*>(&g_kl[base + (size_t)r*NH + c4]);
  }
  for (int idx4 = t; idx4 < nk*16; idx4 += 256){
    int s = idx4 >> 4, h4 = (idx4 & 15) << 2;
    uint2 vh2 = *reinterpret_cast<const uint2*>(&g_vh[base + (size_t)s*NH + h4]);
    uint2 vl2 = *reinterpret_cast<const uint2*>(&g_vl[base + (size_t)s*NH + h4]);
    const __nv_bfloat162* ph = reinterpret_cast<const __nv_bfloat162*>(&vh2);
    const __nv_bfloat162* pl = reinterpret_cast<const __nv_bfloat162*>(&vl2);
    vth[(h4+0)*VSTR + s] = ph[0].x;  vth[(h4+1)*VSTR + s] = ph[0].y;
    vth[(h4+2)*VSTR + s] = ph[1].x;  vth[(h4+3)*VSTR + s] = ph[1].y;
    vtl[(h4+0)*VSTR + s] = pl[0].x;  vtl[(h4+1)*VSTR + s] = pl[0].y;
    vtl[(h4+2)*VSTR + s] = pl[1].x;  vtl[(h4+3)*VSTR + s] = pl[1].y;
  }
  __syncthreads();

  const int rb  = blk*128 + w*16;
  const int lrb = w*16;

  // hoist Q fragments (loop-invariant over j)
  uint32_t qa[4][4], qla[4][4];
  #pragma unroll
  for (int ks = 0; ks < 4; ks++){
    int ko = ks*16;
    qa[ks][0]  = *reinterpret_cast<const uint32_t*>(&qh[(lrb+g  )*72 + ko + 2*t4    ]);
    qa[ks][1]  = *reinterpret_cast<const uint32_t*>(&qh[(lrb+g+8)*72 + ko + 2*t4    ]);
    qa[ks][2]  = *reinterpret_cast<const uint32_t*>(&qh[(lrb+g  )*72 + ko + 2*t4 + 8]);
    qa[ks][3]  = *reinterpret_cast<const uint32_t*>(&qh[(lrb+g+8)*72 + ko + 2*t4 + 8]);
    qla[ks][0] = *reinterpret_cast<const uint32_t*>(&ql[(lrb+g  )*72 + ko + 2*t4    ]);
    qla[ks][1] = *reinterpret_cast<const uint32_t*>(&ql[(lrb+g+8)*72 + ko + 2*t4    ]);
    qla[ks][2] = *reinterpret_cast<const uint32_t*>(&ql[(lrb+g  )*72 + ko + 2*t4 + 8]);
    qla[ks][3] = *reinterpret_cast<const uint32_t*>(&ql[(lrb+g+8)*72 + ko + 2*t4 + 8]);
  }

  float m_[2] = {-1e30f, -1e30f};
  float l_[2] = {0.f, 0.f};
  float o[8][4];
  #pragma unroll
  for (int nt = 0; nt < 8; nt++)
    #pragma unroll
    for (int e = 0; e < 4; e++) o[nt][e] = 0.f;

  const int jmax = (rb + 15) >> 6;
  for (int j = 0; j <= jmax; j++){
    float s[8][4];
    #pragma unroll
    for (int nt = 0; nt < 8; nt++)
      #pragma unroll
      for (int e = 0; e < 4; e++) s[nt][e] = 0.f;

    #pragma unroll
    for (int ks = 0; ks < 4; ks++){
      int ko = ks*16;
      uint32_t kb[8][2];
      #pragma unroll
      for (int nt = 0; nt < 8; nt++){
        int kr = j*64 + nt*8 + g;
        kb[nt][0] = *reinterpret_cast<const uint32_t*>(&kh[kr*72 + ko + 2*t4    ]);
        kb[nt][1] = *reinterpret_cast<const uint32_t*>(&kh[kr*72 + ko + 2*t4 + 8]);
      }
      #pragma unroll
      for (int nt = 0; nt < 8; nt++) mma16816(s[nt], qa[ks],  kb[nt]);   // qh*kh
      #pragma unroll
      for (int nt = 0; nt < 8; nt++) mma16816(s[nt], qla[ks], kb[nt]);   // ql*kh
      #pragma unroll
      for (int nt = 0; nt < 8; nt++){
        int kr = j*64 + nt*8 + g;
        kb[nt][0] = *reinterpret_cast<const uint32_t*>(&kl[kr*72 + ko + 2*t4    ]);
        kb[nt][1] = *reinterpret_cast<const uint32_t*>(&kl[kr*72 + ko + 2*t4 + 8]);
      }
      #pragma unroll
      for (int nt = 0; nt < 8; nt++) mma16816(s[nt], qa[ks],  kb[nt]);   // qh*kl
    }

    const bool needm = (j*64 + 63 > rb);
    #pragma unroll
    for (int nt = 0; nt < 8; nt++){
      #pragma unroll
      for (int e = 0; e < 4; e++){
        float v = s[nt][e] * 0.125f;
        if (needm){
          int col = j*64 + nt*8 + 2*t4 + (e & 1);
          int row = rb + g + ((e & 2) ? 8 : 0);
          if (col > row) v = -1e30f;
        }
        s[nt][e] = v;
      }
    }

    float mx0 = -1e30f, mx1 = -1e30f;
    #pragma unroll
    for (int nt = 0; nt < 8; nt++){
      mx0 = fmaxf(mx0, fmaxf(s[nt][0], s[nt][1]));
      mx1 = fmaxf(mx1, fmaxf(s[nt][2], s[nt][3]));
    }
    mx0 = fmaxf(mx0, __shfl_xor_sync(0xffffffffu, mx0, 1));
    mx0 = fmaxf(mx0, __shfl_xor_sync(0xffffffffu, mx0, 2));
    mx1 = fmaxf(mx1, __shfl_xor_sync(0xffffffffu, mx1, 1));
    mx1 = fmaxf(mx1, __shfl_xor_sync(0xffffffffu, mx1, 2));
    float mn0 = fmaxf(m_[0], mx0), mn1 = fmaxf(m_[1], mx1);
    float cr0 = __expf(m_[0] - mn0), cr1 = __expf(m_[1] - mn1);
    m_[0] = mn0; m_[1] = mn1;

    float rs0 = 0.f, rs1 = 0.f;
    #pragma unroll
    for (int nt = 0; nt < 8; nt++){
      s[nt][0] = __expf(s[nt][0] - mn0); rs0 += s[nt][0];
      s[nt][1] = __expf(s[nt][1] - mn0); rs0 += s[nt][1];
      s[nt][2] = __expf(s[nt][2] - mn1); rs1 += s[nt][2];
      s[nt][3] = __expf(s[nt][3] - mn1); rs1 += s[nt][3];
    }
    rs0 += __shfl_xor_sync(0xffffffffu, rs0, 1);
    rs0 += __shfl_xor_sync(0xffffffffu, rs0, 2);
    rs1 += __shfl_xor_sync(0xffffffffu, rs1, 1);
    rs1 += __shfl_xor_sync(0xffffffffu, rs1, 2);
    l_[0] = l_[0]*cr0 + rs0;
    l_[1] = l_[1]*cr1 + rs1;
    #pragma unroll
    for (int nt = 0; nt < 8; nt++){
      o[nt][0] *= cr0; o[nt][1] *= cr0;
      o[nt][2] *= cr1; o[nt][3] *= cr1;
    }

    #pragma unroll
    for (int ks2 = 0; ks2 < 4; ks2++){
      uint32_t ph[4], pl[4];
      ph[0] = pack_hi2(s[2*ks2  ][0], s[2*ks2  ][1]);
      ph[1] = pack_hi2(s[2*ks2  ][2], s[2*ks2  ][3]);
      ph[2] = pack_hi2(s[2*ks2+1][0], s[2*ks2+1][1]);
      ph[3] = pack_hi2(s[2*ks2+1][2], s[2*ks2+1][3]);
      pl[0] = pack_lo2(s[2*ks2  ][0], s[2*ks2  ][1]);
      pl[1] = pack_lo2(s[2*ks2  ][2], s[2*ks2  ][3]);
      pl[2] = pack_lo2(s[2*ks2+1][0], s[2*ks2+1][1]);
      pl[3] = pack_lo2(s[2*ks2+1][2], s[2*ks2+1][3]);
      int sb2 = j*64 + ks2*16;
      uint32_t vb[8][2];
      #pragma unroll
      for (int nt2 = 0; nt2 < 8; nt2++){
        vb[nt2][0] = *reinterpret_cast<const uint32_t*>(&vth[(nt2*8+g)*VSTR + sb2 + 2*t4    ]);
        vb[nt2][1] = *reinterpret_cast<const uint32_t*>(&vth[(nt2*8+g)*VSTR + sb2 + 2*t4 + 8]);
      }
      #pragma unroll
      for (int nt2 = 0; nt2 < 8; nt2++) mma16816(o[nt2], ph, vb[nt2]);   // ph*vh
      #pragma unroll
      for (int nt2 = 0; nt2 < 8; nt2++) mma16816(o[nt2], pl, vb[nt2]);   // pl*vh
      #pragma unroll
      for (int nt2 = 0; nt2 < 8; nt2++){
        vb[nt2][0] = *reinterpret_cast<const uint32_t*>(&vtl[(nt2*8+g)*VSTR + sb2 + 2*t4    ]);
        vb[nt2][1] = *reinterpret_cast<const uint32_t*>(&vtl[(nt2*8+g)*VSTR + sb2 + 2*t4 + 8]);
      }
      #pragma unroll
      for (int nt2 = 0; nt2 < 8; nt2++) mma16816(o[nt2], ph, vb[nt2]);   // ph*vl
    }
  }

  float inv0 = 1.f / l_[0], inv1 = 1.f / l_[1];
  #pragma unroll
  for (int nt2 = 0; nt2 < 8; nt2++){
    int col = nt2*8 + 2*t4;
    size_t o0 = base + (size_t)(rb + g)*NH + col;
    float2 v01 = make_float2(o[nt2][0]*inv0, o[nt2][1]*inv0);
    float2 v23 = make_float2(o[nt2][2]*inv1, o[nt2][3]*inv1);
    *reinterpret_cast<float2*>(&out[o0])        = v01;
    *reinterpret_cast<float2*>(&out[o0 + 8*NH]) = v23;
  }
}

// ---------------- launch ----------------
extern "C" void kernel_launch(void* const* d_in, const int* in_sizes, int n_in,
                              void* d_out, int out_size){
  const float* x  = (const float*)d_in[0];
  const float* Wq = (const float*)d_in[1];
  const float* Wk = (const float*)d_in[2];
  const float* Wv = (const float*)d_in[3];
  float* out = (float*)d_out;

  cudaFuncSetAttribute(qkv_kernel,  cudaFuncAttributeMaxDynamicSharedMemorySize, K1_SMEM);
  cudaFuncSetAttribute(attn_kernel, cudaFuncAttributeMaxDynamicSharedMemorySize, K2_SMEM);

  prep_w_kernel<<<384, 256>>>(Wq, Wk, Wv);
  qkv_kernel<<<2048, 256, K1_SMEM>>>(x);
  attn_kernel<<<2048, 256, K2_SMEM>>>(out);
}

// round 9
// speedup vs baseline: 2.2737x; 2.2737x over previous
#include <cuda_runtime.h>
#include <cuda_fp16.h>
#include <cstdint>

#define NB 1024
#define NT 256
#define NC 512
#define NH 64

// ---------------- scratch (static device globals; no allocation) ----------------
__device__ __half g_q[NB*NT*NH];
__device__ __half g_k[NB*NT*NH];
__device__ __half g_v[NB*NT*NH];
__device__ __half g_wt[192*512];           // [n192][k] transposed fp16

// ---------------- helpers ----------------
__device__ __forceinline__ uint32_t smem_u32(const void* p){
  uint32_t a;
  asm("{ .reg .u64 t; cvta.to.shared.u64 t, %1; cvt.u32.u64 %0, t; }" : "=r"(a) : "l"(p));
  return a;
}
// fp16 MMA, fp32 accumulate
__device__ __forceinline__ void mma16816f(float* d, const uint32_t* a, const uint32_t* b){
  asm volatile(
    "mma.sync.aligned.m16n8k16.row.col.f32.f16.f16.f32 "
    "{%0,%1,%2,%3},{%4,%5,%6,%7},{%8,%9},{%0,%1,%2,%3};\n"
    : "+f"(d[0]), "+f"(d[1]), "+f"(d[2]), "+f"(d[3])
    : "r"(a[0]), "r"(a[1]), "r"(a[2]), "r"(a[3]), "r"(b[0]), "r"(b[1]));
}
__device__ __forceinline__ void cp_async16(uint32_t saddr, const void* g){
  asm volatile("cp.async.cg.shared.global [%0], [%1], 16;" :: "r"(saddr), "l"(g));
}
#define CP_COMMIT() asm volatile("cp.async.commit_group;" ::: "memory")
#define CP_WAIT0()  asm volatile("cp.async.wait_group 0;" ::: "memory")

__device__ __forceinline__ uint32_t packh2(float a, float b){
  __half2 t = __floats2half2_rn(a, b);
  return *reinterpret_cast<uint32_t*>(&t);
}

// ---------------- kernel 0: transpose weights to fp16 ----------------
__global__ void prep_w_kernel(const float* __restrict__ Wq,
                              const float* __restrict__ Wk,
                              const float* __restrict__ Wv){
  int idx = blockIdx.x*blockDim.x + threadIdx.x;
  if (idx >= 192*512) return;
  int n192 = idx >> 9, k = idx & 511;
  int mat = n192 >> 6, n = n192 & 63;
  const float* W = (mat == 0) ? Wq : (mat == 1 ? Wk : Wv);
  g_wt[idx] = __float2half_rn(W[k*NH + n]);
}

// ---------------- kernel 1: fused QKV projection (fp16 single-pass MMA) ----------------
// CTA: 128 rows x 192 cols (Q|K|V), K-chunks of 64. 8 warps = 2(m) x 4(n), warp tile 64x48.
// smem (halves): x[9216] | Wbuf0[13824] | Wbuf1[13824]
#define K1_WOFF  9216
#define K1_WBUF  13824
#define K1_SMEM  ((9216 + 2*13824)*2)

__global__ __launch_bounds__(256, 1) void qkv_kernel(const float* __restrict__ x){
  extern __shared__ __half sm1[];
  __half* xs = sm1;
  const uint32_t sb = smem_u32(sm1);

  const int t = threadIdx.x;
  const int w = t >> 5, lane = t & 31, g = lane >> 2, t4 = lane & 3;
  const int mw = w >> 2, nw = w & 3;          // 2(m) x 4(n)
  const int row0 = blockIdx.x * 128;

  float acc[4][6][4];
  #pragma unroll
  for (int mt = 0; mt < 4; mt++)
    #pragma unroll
    for (int nt = 0; nt < 6; nt++)
      #pragma unroll
      for (int e = 0; e < 4; e++) acc[mt][nt][e] = 0.f;

  float4 xr[8];

  #define LDG_X(kc) { \
    _Pragma("unroll") \
    for (int i = 0; i < 8; i++){ \
      int idx4 = i*256 + t; \
      int r = idx4 >> 4, c4 = (idx4 & 15) << 2; \
      xr[i] = *reinterpret_cast<const float4*>(x + (size_t)(row0 + r)*NC + (kc)*64 + c4); \
    } }

  #define STS_X() { \
    _Pragma("unroll") \
    for (int i = 0; i < 8; i++){ \
      int idx4 = i*256 + t; \
      int r = idx4 >> 4, c4 = (idx4 & 15) << 2; \
      float4 v = xr[i]; \
      __half2 h01 = __floats2half2_rn(v.x, v.y); \
      __half2 h23 = __floats2half2_rn(v.z, v.w); \
      *reinterpret_cast<__half2*>(&xs[r*72 + c4    ]) = h01; \
      *reinterpret_cast<__half2*>(&xs[r*72 + c4 + 2]) = h23; \
    } }

  // W tile (192x64 fp16) for chunk kc -> buffer b via cp.async; 1536 x 16B chunks
  #define CPA_W(kc, b) { \
    _Pragma("unroll") \
    for (int i = 0; i < 6; i++){ \
      int idx = i*256 + t; \
      int n = idx >> 3, c8 = idx & 7; \
      const __half* src = g_wt + n*512 + (kc)*64 + c8*8; \
      uint32_t dst = sb + (uint32_t)(K1_WOFF + (b)*K1_WBUF + n*72 + c8*8) * 2u; \
      cp_async16(dst, src); \
    } \
    CP_COMMIT(); }

  // prologue
  LDG_X(0); STS_X(); CPA_W(0, 0);

  for (int kc = 0; kc < 8; kc++){
    const int buf = kc & 1;
    CP_WAIT0();
    __syncthreads();

    if (kc < 7){
      CPA_W(kc+1, buf^1);
      LDG_X(kc+1);
    }

    const __half* wb = sm1 + K1_WOFF + buf*K1_WBUF;

    #pragma unroll
    for (int ks = 0; ks < 4; ks++){
      const int ko = ks*16;
      uint32_t ah[4][4];
      #pragma unroll
      for (int mt = 0; mt < 4; mt++){
        int rb = mw*64 + mt*16;
        ah[mt][0] = *reinterpret_cast<const uint32_t*>(&xs[(rb+g  )*72 + ko + 2*t4    ]);
        ah[mt][1] = *reinterpret_cast<const uint32_t*>(&xs[(rb+g+8)*72 + ko + 2*t4    ]);
        ah[mt][2] = *reinterpret_cast<const uint32_t*>(&xs[(rb+g  )*72 + ko + 2*t4 + 8]);
        ah[mt][3] = *reinterpret_cast<const uint32_t*>(&xs[(rb+g+8)*72 + ko + 2*t4 + 8]);
      }
      uint32_t bb[6][2];
      #pragma unroll
      for (int nt = 0; nt < 6; nt++){
        int nb = nw*48 + nt*8;
        bb[nt][0] = *reinterpret_cast<const uint32_t*>(&wb[(nb+g)*72 + ko + 2*t4    ]);
        bb[nt][1] = *reinterpret_cast<const uint32_t*>(&wb[(nb+g)*72 + ko + 2*t4 + 8]);
      }
      #pragma unroll
      for (int nt = 0; nt < 6; nt++)
        #pragma unroll
        for (int mt = 0; mt < 4; mt++) mma16816f(acc[mt][nt], ah[mt], bb[nt]);
    }

    __syncthreads();
    if (kc < 7){ STS_X(); }
  }

  // epilogue: fp32 accum -> fp16 scratch
  #pragma unroll
  for (int mt = 0; mt < 4; mt++){
    #pragma unroll
    for (int nt = 0; nt < 6; nt++){
      int col = nw*48 + nt*8 + 2*t4;
      int mat = col >> 6, h = col & 63;
      __half* dst = (mat == 0) ? g_q : (mat == 1 ? g_k : g_v);
      int r0g = row0 + mw*64 + mt*16 + g;
      *reinterpret_cast<__half2*>(&dst[(size_t)r0g*NH + h]) =
          __floats2half2_rn(acc[mt][nt][0], acc[mt][nt][1]);
      *reinterpret_cast<__half2*>(&dst[(size_t)(r0g+8)*NH + h]) =
          __floats2half2_rn(acc[mt][nt][2], acc[mt][nt][3]);
    }
  }
  #undef LDG_X
  #undef STS_X
  #undef CPA_W
}

// ---------------- kernel 2: causal attention (flash-style, fp16 single-pass MMA) ----------------
// smem (halves): q[9216] | k[18432] | vt[64*266]
#define A_Q  0
#define A_K  9216
#define A_V  27648
#define VSTR 266
#define A_TOT (A_V + 64*VSTR)
#define K2_SMEM (A_TOT*2)

__global__ __launch_bounds__(256, 2) void attn_kernel(float* __restrict__ out){
  extern __shared__ __half sm2[];
  __half* qs = sm2 + A_Q;
  __half* ks = sm2 + A_K;
  __half* vt = sm2 + A_V;

  const int b   = blockIdx.x >> 1;
  const int blk = blockIdx.x & 1;
  const int t = threadIdx.x, w = t >> 5, lane = t & 31, g = lane >> 2, t4 = lane & 3;
  const int nk = (blk + 1) * 128;
  const size_t base = (size_t)b * (NT*NH);

  // stage Q (128 rows)
  #pragma unroll
  for (int i = 0; i < 8; i++){
    int idx4 = i*256 + t;
    int r = idx4 >> 4, c4 = (idx4 & 15) << 2;
    *reinterpret_cast<uint2*>(&qs[r*72 + c4]) =
        *reinterpret_cast<const uint2*>(&g_q[base + (size_t)(blk*128 + r)*NH + c4]);
  }
  // stage K (rows 0..nk)
  for (int idx4 = t; idx4 < nk*16; idx4 += 256){
    int r = idx4 >> 4, c4 = (idx4 & 15) << 2;
    *reinterpret_cast<uint2*>(&ks[r*72 + c4]) =
        *reinterpret_cast<const uint2*>(&g_k[base + (size_t)r*NH + c4]);
  }
  // stage V transposed: vt[h][s]
  for (int idx4 = t; idx4 < nk*16; idx4 += 256){
    int s = idx4 >> 4, h4 = (idx4 & 15) << 2;
    uint2 v2 = *reinterpret_cast<const uint2*>(&g_v[base + (size_t)s*NH + h4]);
    const __half2* pv = reinterpret_cast<const __half2*>(&v2);
    vt[(h4+0)*VSTR + s] = __low2half(pv[0]);  vt[(h4+1)*VSTR + s] = __high2half(pv[0]);
    vt[(h4+2)*VSTR + s] = __low2half(pv[1]);  vt[(h4+3)*VSTR + s] = __high2half(pv[1]);
  }
  __syncthreads();

  const int rb  = blk*128 + w*16;
  const int lrb = w*16;

  // hoist Q fragments (loop-invariant over j)
  uint32_t qa[4][4];
  #pragma unroll
  for (int ks_ = 0; ks_ < 4; ks_++){
    int ko = ks_*16;
    qa[ks_][0] = *reinterpret_cast<const uint32_t*>(&qs[(lrb+g  )*72 + ko + 2*t4    ]);
    qa[ks_][1] = *reinterpret_cast<const uint32_t*>(&qs[(lrb+g+8)*72 + ko + 2*t4    ]);
    qa[ks_][2] = *reinterpret_cast<const uint32_t*>(&qs[(lrb+g  )*72 + ko + 2*t4 + 8]);
    qa[ks_][3] = *reinterpret_cast<const uint32_t*>(&qs[(lrb+g+8)*72 + ko + 2*t4 + 8]);
  }

  float m_[2] = {-1e30f, -1e30f};
  float l_[2] = {0.f, 0.f};
  float o[8][4];
  #pragma unroll
  for (int nt = 0; nt < 8; nt++)
    #pragma unroll
    for (int e = 0; e < 4; e++) o[nt][e] = 0.f;

  const int jmax = (rb + 15) >> 6;
  for (int j = 0; j <= jmax; j++){
    float s[8][4];
    #pragma unroll
    for (int nt = 0; nt < 8; nt++)
      #pragma unroll
      for (int e = 0; e < 4; e++) s[nt][e] = 0.f;

    // ---- S = Q K^T ----
    #pragma unroll
    for (int ks_ = 0; ks_ < 4; ks_++){
      int ko = ks_*16;
      #pragma unroll
      for (int nt = 0; nt < 8; nt++){
        int kr = j*64 + nt*8 + g;
        uint32_t kb[2];
        kb[0] = *reinterpret_cast<const uint32_t*>(&ks[kr*72 + ko + 2*t4    ]);
        kb[1] = *reinterpret_cast<const uint32_t*>(&ks[kr*72 + ko + 2*t4 + 8]);
        mma16816f(s[nt], qa[ks_], kb);
      }
    }

    // ---- scale + causal mask ----
    const bool needm = (j*64 + 63 > rb);
    #pragma unroll
    for (int nt = 0; nt < 8; nt++){
      #pragma unroll
      for (int e = 0; e < 4; e++){
        float v = s[nt][e] * 0.125f;
        if (needm){
          int col = j*64 + nt*8 + 2*t4 + (e & 1);
          int row = rb + g + ((e & 2) ? 8 : 0);
          if (col > row) v = -1e30f;
        }
        s[nt][e] = v;
      }
    }

    // ---- online softmax ----
    float mx0 = -1e30f, mx1 = -1e30f;
    #pragma unroll
    for (int nt = 0; nt < 8; nt++){
      mx0 = fmaxf(mx0, fmaxf(s[nt][0], s[nt][1]));
      mx1 = fmaxf(mx1, fmaxf(s[nt][2], s[nt][3]));
    }
    mx0 = fmaxf(mx0, __shfl_xor_sync(0xffffffffu, mx0, 1));
    mx0 = fmaxf(mx0, __shfl_xor_sync(0xffffffffu, mx0, 2));
    mx1 = fmaxf(mx1, __shfl_xor_sync(0xffffffffu, mx1, 1));
    mx1 = fmaxf(mx1, __shfl_xor_sync(0xffffffffu, mx1, 2));
    float mn0 = fmaxf(m_[0], mx0), mn1 = fmaxf(m_[1], mx1);
    float cr0 = __expf(m_[0] - mn0), cr1 = __expf(m_[1] - mn1);
    m_[0] = mn0; m_[1] = mn1;

    float rs0 = 0.f, rs1 = 0.f;
    #pragma unroll
    for (int nt = 0; nt < 8; nt++){
      s[nt][0] = __expf(s[nt][0] - mn0); rs0 += s[nt][0];
      s[nt][1] = __expf(s[nt][1] - mn0); rs0 += s[nt][1];
      s[nt][2] = __expf(s[nt][2] - mn1); rs1 += s[nt][2];
      s[nt][3] = __expf(s[nt][3] - mn1); rs1 += s[nt][3];
    }
    rs0 += __shfl_xor_sync(0xffffffffu, rs0, 1);
    rs0 += __shfl_xor_sync(0xffffffffu, rs0, 2);
    rs1 += __shfl_xor_sync(0xffffffffu, rs1, 1);
    rs1 += __shfl_xor_sync(0xffffffffu, rs1, 2);
    l_[0] = l_[0]*cr0 + rs0;
    l_[1] = l_[1]*cr1 + rs1;
    #pragma unroll
    for (int nt = 0; nt < 8; nt++){
      o[nt][0] *= cr0; o[nt][1] *= cr0;
      o[nt][2] *= cr1; o[nt][3] *= cr1;
    }

    // ---- O += P V ----
    #pragma unroll
    for (int ks2 = 0; ks2 < 4; ks2++){
      uint32_t ph[4];
      ph[0] = packh2(s[2*ks2  ][0], s[2*ks2  ][1]);
      ph[1] = packh2(s[2*ks2  ][2], s[2*ks2  ][3]);
      ph[2] = packh2(s[2*ks2+1][0], s[2*ks2+1][1]);
      ph[3] = packh2(s[2*ks2+1][2], s[2*ks2+1][3]);
      int sb2 = j*64 + ks2*16;
      #pragma unroll
      for (int nt2 = 0; nt2 < 8; nt2++){
        uint32_t vb[2];
        vb[0] = *reinterpret_cast<const uint32_t*>(&vt[(nt2*8+g)*VSTR + sb2 + 2*t4    ]);
        vb[1] = *reinterpret_cast<const uint32_t*>(&vt[(nt2*8+g)*VSTR + sb2 + 2*t4 + 8]);
        mma16816f(o[nt2], ph, vb);
      }
    }
  }

  // ---- epilogue ----
  float inv0 = 1.f / l_[0], inv1 = 1.f / l_[1];
  #pragma unroll
  for (int nt2 = 0; nt2 < 8; nt2++){
    int col = nt2*8 + 2*t4;
    size_t o0 = base + (size_t)(rb + g)*NH + col;
    float2 v01 = make_float2(o[nt2][0]*inv0, o[nt2][1]*inv0);
    float2 v23 = make_float2(o[nt2][2]*inv1, o[nt2][3]*inv1);
    *reinterpret_cast<float2*>(&out[o0])        = v01;
    *reinterpret_cast<float2*>(&out[o0 + 8*NH]) = v23;
  }
}

// ---------------- launch ----------------
extern "C" void kernel_launch(void* const* d_in, const int* in_sizes, int n_in,
                              void* d_out, int out_size){
  const float* x  = (const float*)d_in[0];
  const float* Wq = (const float*)d_in[1];
  const float* Wk = (const float*)d_in[2];
  const float* Wv = (const float*)d_in[3];
  float* out = (float*)d_out;

  cudaFuncSetAttribute(qkv_kernel,  cudaFuncAttributeMaxDynamicSharedMemorySize, K1_SMEM);
  cudaFuncSetAttribute(attn_kernel, cudaFuncAttributeMaxDynamicSharedMemorySize, K2_SMEM);

  prep_w_kernel<<<384, 256>>>(Wq, Wk, Wv);
  qkv_kernel<<<2048, 256, K1_SMEM>>>(x);
  attn_kernel<<<2048, 256, K2_SMEM>>>(out);
}